// round 1
// baseline (speedup 1.0000x reference)
#include <cuda_runtime.h>

// Problem constants (from reference)
#define F_FIELDS 17
#define HH 300
#define WW 400
#define H_F 38
#define W_F 50
#define NPTS (F_FIELDS * H_F * W_F)          // 32300 source points
#define RADIUS 13
#define W_WIN (2 * RADIUS + 1)               // 27
#define NCELL (W_WIN * W_WIN)                // 729
#define OUT_ELEMS (F_FIELDS * HH * WW)       // 2,040,000

// One block per source point. Each block splats that point's 27x27 truncated
// Gaussian window into the output heatmap with global atomic adds.
__global__ void __launch_bounds__(256) cifhr_scatter_kernel(
    const float* __restrict__ x,   // (17, 5, 38, 50)
    float* __restrict__ out        // (17, 300, 400), pre-initialized to cifhr
) {
    const int p = blockIdx.x;                 // point index
    const int f = p / (H_F * W_F);
    const int hw = p - f * (H_F * W_F);

    const float* base = x + (size_t)f * 5 * (H_F * W_F) + hw;
    const float v = base[0];
    // valid = (v >= V_TH) & (scale * STRIDE >= MIN_SCALE); MIN_SCALE = 0
    if (!(v >= 0.1f)) return;                 // whole block exits together
    const float scale = base[4 * H_F * W_F];
    if (!(scale * 8.0f >= 0.0f)) return;

    const float px = base[1 * H_F * W_F] * 8.0f;
    const float py = base[2 * H_F * W_F] * 8.0f;

    const float sigma  = fmaxf(1.0f, 0.5f * scale * 8.0f);
    const float sigma2 = sigma * sigma;
    const float trunc2 = 4.0f * sigma2;
    const float neg_half_inv_s2 = -0.5f / sigma2;
    const float value = v * (1.0f / 16.0f);   // v / NEIGHBORS * FACTOR

    // jnp.round = round-half-to-even = rintf (default FE rounding)
    const int cx = (int)rintf(px);
    const int cy = (int)rintf(py);

    float* fout = out + (size_t)f * HH * WW;

    for (int i = threadIdx.x; i < NCELL; i += blockDim.x) {
        const int dy = i / W_WIN - RADIUS;
        const int dx = i % W_WIN - RADIUS;
        const int yy = cy + dy;
        const int xx = cx + dx;
        if (yy < 0 || yy >= HH || xx < 0 || xx >= WW) continue;

        const float fdy = (float)yy - py;
        const float fdx = (float)xx - px;
        const float dy2 = fdy * fdy;
        const float dx2 = fdx * fdx;
        const float d2 = dy2 + dx2;
        if (!(d2 <= trunc2)) continue;

        float g;
        if (dy2 < 0.25f && dx2 < 0.25f) {
            g = 1.0f;                         // "nearest" cell override
        } else {
            // approx_exp(t) = (1 + t/8)^8, t = -0.5*d2/sigma2
            float t = 1.0f + (neg_half_inv_s2 * d2) * 0.125f;
            t = t * t;
            t = t * t;
            t = t * t;
            g = t;
        }
        atomicAdd(fout + yy * WW + xx, value * g);
    }
}

__global__ void cifhr_clamp_kernel(float* __restrict__ out, int n) {
    int i = blockIdx.x * blockDim.x + threadIdx.x;
    if (i < n) {
        out[i] = fminf(out[i], 1.0f);
    }
}

extern "C" void kernel_launch(void* const* d_in, const int* in_sizes, int n_in,
                              void* d_out, int out_size) {
    const float* cifhr = (const float*)d_in[0];   // (17,300,400) zeros
    const float* x     = (const float*)d_in[1];   // (17,5,38,50)
    float* out = (float*)d_out;

    // 1) out <- cifhr  (graph-capturable async D2D copy)
    cudaMemcpyAsync(out, cifhr, (size_t)OUT_ELEMS * sizeof(float),
                    cudaMemcpyDeviceToDevice, 0);

    // 2) scatter Gaussian contributions
    cifhr_scatter_kernel<<<NPTS, 256>>>(x, out);

    // 3) clamp to 1.0
    const int threads = 256;
    const int blocks = (OUT_ELEMS + threads - 1) / threads;
    cifhr_clamp_kernel<<<blocks, threads>>>(out, OUT_ELEMS);
}

// round 3
// speedup vs baseline: 2.1189x; 2.1189x over previous
#include <cuda_runtime.h>

#define F_FIELDS 17
#define HH 300
#define WW 400
#define H_F 38
#define W_F 50
#define NPTS (F_FIELDS * H_F * W_F)          // 32300
#define OUT_ELEMS (F_FIELDS * HH * WW)       // 2,040,000

// One warp per point. Bounding box restricted to the truncation disc, rows
// covered by aligned 4-float groups, accumulated with red.global.add.v4.f32.
__global__ void __launch_bounds__(256) cifhr_scatter_v4(
    const float* __restrict__ x,   // (17, 5, 38, 50)
    float* __restrict__ out        // (17, 300, 400)
) {
    const int warp = threadIdx.x >> 5;
    const int lane = threadIdx.x & 31;
    const int p = blockIdx.x * 8 + warp;
    if (p >= NPTS) return;

    const int f = p / (H_F * W_F);
    const int hw = p - f * (H_F * W_F);
    const float* base = x + (size_t)f * 5 * (H_F * W_F) + hw;

    const float v = base[0];
    if (!(v >= 0.1f)) return;                       // v >= V_TH
    const float scale = base[4 * H_F * W_F];
    if (!(scale * 8.0f >= 0.0f)) return;            // MIN_SCALE = 0

    const float px = base[1 * H_F * W_F] * 8.0f;
    const float py = base[2 * H_F * W_F] * 8.0f;

    const float sigma  = fmaxf(1.0f, 4.0f * scale); // max(1, 0.5*scale*8)
    const float sigma2 = sigma * sigma;
    const float trunc2 = 4.0f * sigma2;
    const float ninv   = -0.5f / sigma2;
    const float value  = v * 0.0625f;               // v/16

    const int cx = (int)rintf(px);                  // round-half-even == jnp.round
    const int cy = (int)rintf(py);

    // |dy| > 2*sigma + 0.5  =>  dy2 = (yy-py)^2 >= (|dy|-0.5)^2 > 4*sigma^2 : fails mask
    int rb = (int)floorf(2.0f * sigma + 0.5f);
    if (rb > 13) rb = 13;

    const int y0 = max(cy - rb, 0), y1 = min(cy + rb, HH - 1);
    const int x0 = max(cx - rb, 0), x1 = min(cx + rb, WW - 1);
    if (y0 > y1 || x0 > x1) return;

    const int xs = x0 & ~3;                         // >= 0
    const int Wg = (((x1 | 3) + 1) - xs) >> 2;      // groups per row; xe <= 400
    const int nrows = y1 - y0 + 1;
    const int Ng = nrows * Wg;                      // total 4-cell groups

    // incremental (row, gx) tracking: only two small divisions per lane
    int row = lane / Wg;
    int gx  = lane - row * Wg;
    const int drow = 32 / Wg;
    const int dgx  = 32 - drow * Wg;

    float* __restrict__ fout = out + (size_t)f * HH * WW;

    for (int g = lane; g < Ng; g += 32, row += drow, gx += dgx) {
        if (gx >= Wg) { gx -= Wg; row += 1; }
        const int yy = y0 + row;
        const int xb = xs + (gx << 2);

        const float fdy = (float)yy - py;
        const float dy2 = fdy * fdy;
        const bool ny = dy2 < 0.25f;

        float c[4];
        #pragma unroll
        for (int j = 0; j < 4; j++) {
            const int xx = xb + j;
            const float fdx = (float)xx - px;
            const float dx2 = fdx * fdx;
            const float d2 = dy2 + dx2;
            // approx_exp(-0.5*d2/sigma2) = (1 + t/8)^8
            float t = fmaf(ninv * d2, 0.125f, 1.0f);
            t = t * t; t = t * t; t = t * t;
            const float gg = (ny && dx2 < 0.25f) ? 1.0f : t;
            const bool in = (xx >= x0) & (xx <= x1) & (d2 <= trunc2);
            c[j] = in ? value * gg : 0.0f;
        }

        if (c[0] != 0.0f || c[1] != 0.0f || c[2] != 0.0f || c[3] != 0.0f) {
            float* addr = fout + yy * WW + xb;      // 16B aligned, within row
            asm volatile("red.global.add.v4.f32 [%0], {%1,%2,%3,%4};"
                         :: "l"(addr), "f"(c[0]), "f"(c[1]), "f"(c[2]), "f"(c[3])
                         : "memory");
        }
    }
}

__global__ void cifhr_clamp4(float4* __restrict__ out, int n4) {
    int i = blockIdx.x * blockDim.x + threadIdx.x;
    if (i < n4) {
        float4 v = out[i];
        v.x = fminf(v.x, 1.0f);
        v.y = fminf(v.y, 1.0f);
        v.z = fminf(v.z, 1.0f);
        v.w = fminf(v.w, 1.0f);
        out[i] = v;
    }
}

extern "C" void kernel_launch(void* const* d_in, const int* in_sizes, int n_in,
                              void* d_out, int out_size) {
    const float* cifhr = (const float*)d_in[0];
    const float* x     = (const float*)d_in[1];
    float* out = (float*)d_out;

    cudaMemcpyAsync(out, cifhr, (size_t)OUT_ELEMS * sizeof(float),
                    cudaMemcpyDeviceToDevice, 0);

    const int warps_per_block = 8;
    const int blocks = (NPTS + warps_per_block - 1) / warps_per_block;
    cifhr_scatter_v4<<<blocks, 256>>>(x, out);

    const int n4 = OUT_ELEMS / 4;
    cifhr_clamp4<<<(n4 + 255) / 256, 256>>>((float4*)out, n4);
}